// round 8
// baseline (speedup 1.0000x reference)
#include <cuda_runtime.h>
#include <cuda_fp16.h>
#include <cstdint>
#include <cstddef>

// out[h,n,m] = LeakyReLU_{0.2}( sum_d z0[n,d]*z1[m,d]*W[h,d] + bias[h] )
// N=M=1024, D=256, H=128, fp32 in/out.
//
// v8: register-resident B (z1) + SMEM A (z0 frags) + L1-resident W via __ldg.
//  - z1 B-frags: 128 regs/lane, loaded once per CTA.
//  - z0 A-frags: 8KB smem slice, one LDS.128 per ks (ring depth 2).
//  - W-frags: __ldg from 64KB table (L1-resident), ring depth 2.
//  - 3 warps/SMSP (<=170 regs), h split into 4 slices -> grid 2048 (4.6 waves).
// Warp tile 16n x 32m; CTA = 4 warps = 16n x 128m x 32h.

#define NT 128

__device__ uint4 g_z0f[64 * 16 * 32];      // [n16tile][ks][lane] {a0,a1,a2,a3}  512KB
__device__ uint4 g_z1f[128 * 8 * 32];      // [m8tile][kspair][lane]             512KB
__device__ uint2 g_wf[128 * 16 * 4];       // [h][ks][c] {w01, w89}              64KB

__device__ __forceinline__ uint32_t smem_u32(const void* p) {
    uint32_t a;
    asm("{ .reg .u64 t; cvta.to.shared.u64 t, %1; cvt.u32.u64 %0, t; }" : "=r"(a) : "l"(p));
    return a;
}

#define CP16(saddr, gptr)                                                     \
    asm volatile("cp.async.cg.shared.global [%0], [%1], 16;"                  \
                 :: "r"(saddr), "l"(gptr))

#define MMA(c, a0, a1, a2, a3, b0, b1)                                        \
    asm volatile("mma.sync.aligned.m16n8k16.row.col.f32.f16.f16.f32 "         \
                 "{%0,%1,%2,%3}, {%4,%5,%6,%7}, {%8,%9}, {%0,%1,%2,%3};"      \
                 : "+f"((c)[0]), "+f"((c)[1]), "+f"((c)[2]), "+f"((c)[3])     \
                 : "r"(a0), "r"(a1), "r"(a2), "r"(a3), "r"(b0), "r"(b1))

#define HMUL2(d, x, y)                                                        \
    asm("mul.f16x2 %0, %1, %2;" : "=r"(d) : "r"(x), "r"(y))

#define LDS128(v, addr)                                                       \
    asm("ld.shared.v4.b32 {%0,%1,%2,%3}, [%4];"                               \
        : "=r"((v).x), "=r"((v).y), "=r"((v).z), "=r"((v).w) : "r"(addr))

// ---------------- prep kernels ----------------

__global__ void prep_z0f(const float* __restrict__ z0) {
    int gid = blockIdx.x * 256 + threadIdx.x;      // 32768 threads
    int t_n = gid >> 9, ks = (gid >> 5) & 15, lane = gid & 31;
    int n = t_n * 16 + (lane >> 2);
    int k0 = ks * 16 + (lane & 3) * 2;
    const float* r0 = z0 + (size_t)n * 256;
    const float* r8 = r0 + 8 * 256;
    float2 p0 = *(const float2*)(r0 + k0);
    float2 p1 = *(const float2*)(r8 + k0);
    float2 p2 = *(const float2*)(r0 + k0 + 8);
    float2 p3 = *(const float2*)(r8 + k0 + 8);
    union { __half2 h[4]; uint4 u; } pk;
    pk.h[0] = __floats2half2_rn(p0.x, p0.y);
    pk.h[1] = __floats2half2_rn(p1.x, p1.y);
    pk.h[2] = __floats2half2_rn(p2.x, p2.y);
    pk.h[3] = __floats2half2_rn(p3.x, p3.y);
    g_z0f[gid] = pk.u;
}

__global__ void prep_z1f(const float* __restrict__ z1) {
    int gid = blockIdx.x * 256 + threadIdx.x;      // 32768 threads
    int t8 = gid >> 8, ksp = (gid >> 5) & 7, lane = gid & 31;
    int m = t8 * 8 + (lane >> 2);
    int ka = ksp * 32 + (lane & 3) * 2;
    const float* r = z1 + (size_t)m * 256;
    float2 a0 = *(const float2*)(r + ka);
    float2 a1 = *(const float2*)(r + ka + 8);
    float2 b0 = *(const float2*)(r + ka + 16);
    float2 b1 = *(const float2*)(r + ka + 24);
    union { __half2 h[4]; uint4 u; } pk;
    pk.h[0] = __floats2half2_rn(a0.x, a0.y);
    pk.h[1] = __floats2half2_rn(a1.x, a1.y);
    pk.h[2] = __floats2half2_rn(b0.x, b0.y);
    pk.h[3] = __floats2half2_rn(b1.x, b1.y);
    g_z1f[gid] = pk.u;
}

__global__ void prep_wf(const float* __restrict__ W) {
    int gid = blockIdx.x * 256 + threadIdx.x;      // 8192 threads
    int h = gid >> 6, ks = (gid >> 2) & 15, c = gid & 3;
    int k0 = ks * 16 + c * 2;
    const float* r = W + (size_t)h * 256;
    float2 p0 = *(const float2*)(r + k0);
    float2 p1 = *(const float2*)(r + k0 + 8);
    union { __half2 h2[2]; uint2 u; } pk;
    pk.h2[0] = __floats2half2_rn(p0.x, p0.y);
    pk.h2[1] = __floats2half2_rn(p1.x, p1.y);
    g_wf[gid] = pk.u;
}

// ---------------- main kernel ----------------

__global__ void __launch_bounds__(NT, 3)
fc_main(const float* __restrict__ bias, float* __restrict__ out)
{
    __shared__ uint4 s_z0[512];                   // 8KB: [ks(16)][lane(32)]
    const uint32_t sbase = smem_u32(s_z0);
    const int tid = threadIdx.x;
    const int wid = tid >> 5;      // 0..3 = m slab
    const int lid = tid & 31;

    const int hs = (int)(blockIdx.x & 3);          // h-slice (32 h)
    const int ms = (int)((blockIdx.x >> 2) & 7);   // m-supertile (128 m)
    const int nt = (int)(blockIdx.x >> 5);         // n-tile (16 n), 0..63

    // Stage z0 frag slice (8KB) into smem
    {
        const uint4* gz = g_z0f + (size_t)nt * 512;
        #pragma unroll
        for (int i = 0; i < 4; ++i)
            CP16(sbase + (uint32_t)((tid + i * 128) * 16), gz + tid + i * 128);
        asm volatile("cp.async.commit_group;" ::: "memory");
    }

    // Persistent z1 B-fragments (128 regs)
    uint4 z1p[4][8];
    {
        #pragma unroll
        for (int u = 0; u < 4; ++u) {
            const uint4* p = g_z1f + ((size_t)(ms * 16 + wid * 4 + u) * 8) * 32 + lid;
            #pragma unroll
            for (int kp = 0; kp < 8; ++kp) z1p[u][kp] = p[kp * 32];
        }
    }

    asm volatile("cp.async.wait_group 0;" ::: "memory");
    __syncthreads();

    const uint32_t zlane = sbase + (uint32_t)(lid * 16);
    const int n_lo = nt * 16 + (lid >> 2);
    const int mb   = ms * 128 + wid * 32 + (lid & 3) * 2;
    const uint2* wcol = g_wf + (lid & 3);          // + h*64 + ks*4

    #pragma unroll 1
    for (int i = 0; i < 32; ++i) {
        const int h = hs * 32 + ((i + wid * 8) & 31);   // per-warp stagger

        float acc[4][4];
        #pragma unroll
        for (int u = 0; u < 4; ++u)
            #pragma unroll
            for (int q = 0; q < 4; ++q) acc[u][q] = 0.0f;

        const uint2* wp = wcol + h * 64;

        // depth-2 rings for z0 frag (LDS.128) and W frag (LDG.64)
        uint4 f0, f1;
        LDS128(f0, zlane);
        LDS128(f1, zlane + 512);
        uint2 w0 = __ldg(wp);
        uint2 w1 = __ldg(wp + 4);

        #pragma unroll
        for (int ks = 0; ks < 16; ++ks) {
            uint4 fN = f1; uint2 wN = w1;
            if (ks < 14) {
                LDS128(fN, zlane + (uint32_t)((ks + 2) * 512));
                wN = __ldg(wp + (ks + 2) * 4);
            }
            uint32_t a0, a1, a2, a3;
            HMUL2(a0, f0.x, w0.x);
            HMUL2(a1, f0.y, w0.x);
            HMUL2(a2, f0.z, w0.y);
            HMUL2(a3, f0.w, w0.y);
            #pragma unroll
            for (int u = 0; u < 4; ++u) {
                const uint32_t b0 = (ks & 1) ? z1p[u][ks >> 1].z : z1p[u][ks >> 1].x;
                const uint32_t b1 = (ks & 1) ? z1p[u][ks >> 1].w : z1p[u][ks >> 1].y;
                MMA(acc[u], a0, a1, a2, a3, b0, b1);
            }
            f0 = f1; f1 = fN;
            w0 = w1; w1 = wN;
        }

        // Epilogue: bias + LeakyReLU + STG.64 streaming
        const float bv = __ldg(bias + h);
        float* ob = out + (((size_t)h) << 20);
        #pragma unroll
        for (int u = 0; u < 4; ++u) {
            const int m = mb + u * 8;
            float2 lo, hi;
            lo.x = acc[u][0] + bv; lo.y = acc[u][1] + bv;
            hi.x = acc[u][2] + bv; hi.y = acc[u][3] + bv;
            lo.x = (lo.x >= 0.f) ? lo.x : 0.2f * lo.x;
            lo.y = (lo.y >= 0.f) ? lo.y : 0.2f * lo.y;
            hi.x = (hi.x >= 0.f) ? hi.x : 0.2f * hi.x;
            hi.y = (hi.y >= 0.f) ? hi.y : 0.2f * hi.y;
            __stcs(reinterpret_cast<float2*>(ob + (size_t)n_lo * 1024 + m), lo);
            __stcs(reinterpret_cast<float2*>(ob + (size_t)(n_lo + 8) * 1024 + m), hi);
        }
    }
}

extern "C" void kernel_launch(void* const* d_in, const int* in_sizes, int n_in,
                              void* d_out, int out_size) {
    const float* z0   = (const float*)d_in[0];   // (1, 1024, 256)
    const float* z1   = (const float*)d_in[1];   // (1, 1024, 256)
    const float* W    = (const float*)d_in[2];   // (128, 256)
    const float* bias = (const float*)d_in[3];   // (128,)
    float* out = (float*)d_out;                  // (1, 128, 1024, 1024)

    prep_z0f<<<128, 256>>>(z0);
    prep_z1f<<<128, 256>>>(z1);
    prep_wf<<<32, 256>>>(W);

    // grid: 64 nt x 8 ms x 4 hs = 2048 CTAs
    fc_main<<<2048, NT>>>(bias, out);
}

// round 9
// speedup vs baseline: 1.3234x; 1.3234x over previous
#include <cuda_runtime.h>
#include <cuda_fp16.h>
#include <cstdint>
#include <cstddef>

// out[h,n,m] = LeakyReLU_{0.2}( sum_d z0[n,d]*z1[m,d]*W[h,d] + bias[h] )
// N=M=1024, D=256, H=128, fp32 in/out.
//
// v9: R7 engine (z0f + z1 frags in regs, W-frag table in smem) with a
// 16n x 16m warp tile so regs ~160 -> 3 CTAs/SM (3 warps/SMSP) to fill
// tensor-pipe bubbles. CTA = 16n x 64m (4 warps), grid = 64nt x 16ms = 1024.

#define NT 128

__device__ uint4 g_z0f[64 * 16 * 32];      // [n16tile][ks][lane] {a0,a1,a2,a3}  512KB
__device__ uint4 g_z1f[128 * 8 * 32];      // [m8tile][kspair][lane]             512KB
__device__ uint2 g_wf[128 * 16 * 4];       // [h][ks][c] {w01, w89}              64KB

static constexpr int SM_BIAS = 65536;
static constexpr int SMEM_BYTES = 65536 + 512;

__device__ __forceinline__ uint32_t smem_u32(const void* p) {
    uint32_t a;
    asm("{ .reg .u64 t; cvta.to.shared.u64 t, %1; cvt.u32.u64 %0, t; }" : "=r"(a) : "l"(p));
    return a;
}

#define CP16(saddr, gptr)                                                     \
    asm volatile("cp.async.cg.shared.global [%0], [%1], 16;"                  \
                 :: "r"(saddr), "l"(gptr))

#define MMA(c, a0, a1, a2, a3, b0, b1)                                        \
    asm volatile("mma.sync.aligned.m16n8k16.row.col.f32.f16.f16.f32 "         \
                 "{%0,%1,%2,%3}, {%4,%5,%6,%7}, {%8,%9}, {%0,%1,%2,%3};"      \
                 : "+f"((c)[0]), "+f"((c)[1]), "+f"((c)[2]), "+f"((c)[3])     \
                 : "r"(a0), "r"(a1), "r"(a2), "r"(a3), "r"(b0), "r"(b1))

#define HMUL2(d, x, y)                                                        \
    asm("mul.f16x2 %0, %1, %2;" : "=r"(d) : "r"(x), "r"(y))

#define LDS_W(w0, w1, addr)                                                   \
    asm("ld.shared.v2.b32 {%0,%1}, [%2];" : "=r"(w0), "=r"(w1) : "r"(addr))

// ---------------- prep kernels ----------------

__global__ void prep_z0f(const float* __restrict__ z0) {
    int gid = blockIdx.x * 256 + threadIdx.x;      // 32768 threads
    int t_n = gid >> 9, ks = (gid >> 5) & 15, lane = gid & 31;
    int n = t_n * 16 + (lane >> 2);
    int k0 = ks * 16 + (lane & 3) * 2;
    const float* r0 = z0 + (size_t)n * 256;
    const float* r8 = r0 + 8 * 256;
    float2 p0 = *(const float2*)(r0 + k0);
    float2 p1 = *(const float2*)(r8 + k0);
    float2 p2 = *(const float2*)(r0 + k0 + 8);
    float2 p3 = *(const float2*)(r8 + k0 + 8);
    union { __half2 h[4]; uint4 u; } pk;
    pk.h[0] = __floats2half2_rn(p0.x, p0.y);
    pk.h[1] = __floats2half2_rn(p1.x, p1.y);
    pk.h[2] = __floats2half2_rn(p2.x, p2.y);
    pk.h[3] = __floats2half2_rn(p3.x, p3.y);
    g_z0f[gid] = pk.u;
}

__global__ void prep_z1f(const float* __restrict__ z1) {
    int gid = blockIdx.x * 256 + threadIdx.x;      // 32768 threads
    int t8 = gid >> 8, ksp = (gid >> 5) & 7, lane = gid & 31;
    int m = t8 * 8 + (lane >> 2);
    int ka = ksp * 32 + (lane & 3) * 2;
    const float* r = z1 + (size_t)m * 256;
    float2 a0 = *(const float2*)(r + ka);
    float2 a1 = *(const float2*)(r + ka + 8);
    float2 b0 = *(const float2*)(r + ka + 16);
    float2 b1 = *(const float2*)(r + ka + 24);
    union { __half2 h[4]; uint4 u; } pk;
    pk.h[0] = __floats2half2_rn(a0.x, a0.y);
    pk.h[1] = __floats2half2_rn(a1.x, a1.y);
    pk.h[2] = __floats2half2_rn(b0.x, b0.y);
    pk.h[3] = __floats2half2_rn(b1.x, b1.y);
    g_z1f[gid] = pk.u;
}

__global__ void prep_wf(const float* __restrict__ W) {
    int gid = blockIdx.x * 256 + threadIdx.x;      // 8192 threads
    int h = gid >> 6, ks = (gid >> 2) & 15, c = gid & 3;
    int k0 = ks * 16 + c * 2;
    const float* r = W + (size_t)h * 256;
    float2 p0 = *(const float2*)(r + k0);
    float2 p1 = *(const float2*)(r + k0 + 8);
    union { __half2 h2[2]; uint2 u; } pk;
    pk.h2[0] = __floats2half2_rn(p0.x, p0.y);
    pk.h2[1] = __floats2half2_rn(p1.x, p1.y);
    g_wf[gid] = pk.u;
}

// ---------------- main kernel ----------------

__global__ void __launch_bounds__(NT, 3)
fc_main(const float* __restrict__ bias, float* __restrict__ out)
{
    extern __shared__ char smem[];
    const uint32_t sbase = smem_u32(smem);
    const int tid = threadIdx.x;
    const int wid = tid >> 5;      // 0..3 = 16m slab
    const int lid = tid & 31;

    const int ms = (int)(blockIdx.x & 15);    // m-supertile (64 m)
    const int nt = (int)(blockIdx.x >> 4);    // n-tile (16 n), 0..63

    // Stage W-frag table (64KB) + bias (512B) into smem
    {
        const uint4* gw = reinterpret_cast<const uint4*>(g_wf);
        #pragma unroll
        for (int i = 0; i < 32; ++i)
            CP16(sbase + (uint32_t)((tid + i * 128) * 16), gw + tid + i * 128);
        if (tid < 32)
            CP16(sbase + SM_BIAS + (uint32_t)(tid * 16),
                 reinterpret_cast<const uint4*>(bias) + tid);
        asm volatile("cp.async.commit_group;" ::: "memory");
    }

    // Persistent fragments: z0 (64 regs), z1 (64 regs)
    uint4 z0f[16];
    {
        const uint4* p = g_z0f + ((size_t)nt * 16) * 32 + lid;
        #pragma unroll
        for (int ks = 0; ks < 16; ++ks) z0f[ks] = p[ks * 32];
    }
    uint4 z1p[2][8];
    {
        #pragma unroll
        for (int u = 0; u < 2; ++u) {
            const uint4* p = g_z1f + ((size_t)(ms * 8 + wid * 2 + u) * 8) * 32 + lid;
            #pragma unroll
            for (int kp = 0; kp < 8; ++kp) z1p[u][kp] = p[kp * 32];
        }
    }

    asm volatile("cp.async.wait_group 0;" ::: "memory");
    __syncthreads();

    const uint32_t wlane = sbase + (uint32_t)((lid & 3) * 8);
    const int n_lo = nt * 16 + (lid >> 2);
    const int mb   = ms * 64 + wid * 16 + (lid & 3) * 2;

    // Per-warp/CTA h-stagger: desync epilogue bursts on each SMSP.
    const int hb = (((int)blockIdx.x << 3) + (wid << 5)) & 127;

    #pragma unroll 1
    for (int i = 0; i < 128; ++i) {
        const int h = (i + hb) & 127;

        float acc[2][4];
        #pragma unroll
        for (int u = 0; u < 2; ++u)
            #pragma unroll
            for (int q = 0; q < 4; ++q) acc[u][q] = 0.0f;

        const uint32_t wbase = wlane + (uint32_t)(h * 512);

        uint32_t wc0, wc1;
        LDS_W(wc0, wc1, wbase);
        #pragma unroll
        for (int ks = 0; ks < 16; ++ks) {
            uint32_t wn0 = wc0, wn1 = wc1;
            if (ks < 15)
                LDS_W(wn0, wn1, wbase + (uint32_t)((ks + 1) * 32));
            uint32_t a0, a1, a2, a3;
            HMUL2(a0, z0f[ks].x, wc0);
            HMUL2(a1, z0f[ks].y, wc0);
            HMUL2(a2, z0f[ks].z, wc1);
            HMUL2(a3, z0f[ks].w, wc1);
            #pragma unroll
            for (int u = 0; u < 2; ++u) {
                const uint32_t b0 = (ks & 1) ? z1p[u][ks >> 1].z : z1p[u][ks >> 1].x;
                const uint32_t b1 = (ks & 1) ? z1p[u][ks >> 1].w : z1p[u][ks >> 1].y;
                MMA(acc[u], a0, a1, a2, a3, b0, b1);
            }
            wc0 = wn0; wc1 = wn1;
        }

        // Epilogue: bias + LeakyReLU + STG.64 streaming
        float bv;
        asm("ld.shared.f32 %0, [%1];" : "=f"(bv) : "r"(sbase + SM_BIAS + (uint32_t)(h * 4)));
        float* ob = out + (((size_t)h) << 20);
        #pragma unroll
        for (int u = 0; u < 2; ++u) {
            const int m = mb + u * 8;
            float2 lo, hi;
            lo.x = acc[u][0] + bv; lo.y = acc[u][1] + bv;
            hi.x = acc[u][2] + bv; hi.y = acc[u][3] + bv;
            lo.x = (lo.x >= 0.f) ? lo.x : 0.2f * lo.x;
            lo.y = (lo.y >= 0.f) ? lo.y : 0.2f * lo.y;
            hi.x = (hi.x >= 0.f) ? hi.x : 0.2f * hi.x;
            hi.y = (hi.y >= 0.f) ? hi.y : 0.2f * hi.y;
            __stcs(reinterpret_cast<float2*>(ob + (size_t)n_lo * 1024 + m), lo);
            __stcs(reinterpret_cast<float2*>(ob + (size_t)(n_lo + 8) * 1024 + m), hi);
        }
    }
}

extern "C" void kernel_launch(void* const* d_in, const int* in_sizes, int n_in,
                              void* d_out, int out_size) {
    const float* z0   = (const float*)d_in[0];   // (1, 1024, 256)
    const float* z1   = (const float*)d_in[1];   // (1, 1024, 256)
    const float* W    = (const float*)d_in[2];   // (128, 256)
    const float* bias = (const float*)d_in[3];   // (128,)
    float* out = (float*)d_out;                  // (1, 128, 1024, 1024)

    prep_z0f<<<128, 256>>>(z0);
    prep_z1f<<<128, 256>>>(z1);
    prep_wf<<<32, 256>>>(W);

    cudaFuncSetAttribute(fc_main, cudaFuncAttributeMaxDynamicSharedMemorySize, SMEM_BYTES);
    // grid: 64 nt x 16 ms = 1024 CTAs
    fc_main<<<1024, NT, SMEM_BYTES>>>(bias, out);
}